// round 15
// baseline (speedup 1.0000x reference)
#include <cuda_runtime.h>
#include <cuda_bf16.h>
#include <cuda_fp16.h>
#include <cstdint>
#include <math.h>

#define BB 4
#define NN 16384
#define CC 256
#define HH 8
#define KK 64
#define DD 32
#define BNTOT (BB*NN)

// ---------------- scratch ----------------
__device__ float g_S[BB*KK*CC];
__device__ float g_denom[BB*KK];
__device__ float g_bias[BNTOT*KK];
__device__ __half g_Xh[BNTOT*CC], g_Xl[BNTOT*CC];
__device__ __half g_Ah[BNTOT*KK];
__device__ __half g_xh[BNTOT*CC];                 // PLANAR [h][n][32] fp16
__device__ __half g_qh[BNTOT*CC];                 // PLANAR [h][n][32] fp16
__device__ __half g_Wqt_hi[CC*CC], g_Wqt_lo[CC*CC];
__device__ __half g_Wpt_hi[CC*CC], g_Wpt_lo[CC*CC];
__device__ __half g_kchi[BB*HH*KK*DD], g_kclo[BB*HH*KK*DD];
__device__ __half g_vcThi[BB*HH*DD*KK], g_vcTlo[BB*HH*DD*KK];

// ---------------- helpers ----------------
__device__ __forceinline__ uint32_t smem_u32(const void* p) {
    uint32_t a;
    asm("{ .reg .u64 t; cvta.to.shared.u64 t, %1; cvt.u32.u64 %0, t; }" : "=r"(a) : "l"(p));
    return a;
}
#define CP16(dst, src) \
    asm volatile("cp.async.cg.shared.global [%0], [%1], 16;" :: "r"(dst), "l"(src))
#define CPCOMMIT() asm volatile("cp.async.commit_group;" ::: "memory")
#define CPWAIT(n)  asm volatile("cp.async.wait_group %0;" :: "n"(n) : "memory")

__device__ __forceinline__ void ldsm_x4(uint32_t* r, uint32_t addr) {
    asm volatile("ldmatrix.sync.aligned.m8n8.x4.shared.b16 {%0,%1,%2,%3}, [%4];"
                 : "=r"(r[0]), "=r"(r[1]), "=r"(r[2]), "=r"(r[3]) : "r"(addr));
}
__device__ __forceinline__ void ldsm_x4_t(uint32_t* r, uint32_t addr) {
    asm volatile("ldmatrix.sync.aligned.m8n8.x4.trans.shared.b16 {%0,%1,%2,%3}, [%4];"
                 : "=r"(r[0]), "=r"(r[1]), "=r"(r[2]), "=r"(r[3]) : "r"(addr));
}
__device__ __forceinline__ void mma_fp16(float* d, const uint32_t* a,
                                         uint32_t b0, uint32_t b1) {
    asm volatile(
        "mma.sync.aligned.m16n8k16.row.col.f32.f16.f16.f32 "
        "{%0,%1,%2,%3}, {%4,%5,%6,%7}, {%8,%9}, {%0,%1,%2,%3};"
        : "+f"(d[0]), "+f"(d[1]), "+f"(d[2]), "+f"(d[3])
        : "r"(a[0]), "r"(a[1]), "r"(a[2]), "r"(a[3]), "r"(b0), "r"(b1));
}
__device__ __forceinline__ uint32_t pack_h2(float a, float b) {
    __half2 h = __floats2half2_rn(a, b);
    return *(uint32_t*)&h;
}

// ---------------- fp16 split of X ----------------
__global__ __launch_bounds__(256) void convertX_kernel(const float* __restrict__ X) {
    size_t i = ((size_t)blockIdx.x * 256 + threadIdx.x) * 8;
    float4 a = *(const float4*)(X + i);
    float4 b = *(const float4*)(X + i + 4);
    float v[8] = {a.x, a.y, a.z, a.w, b.x, b.y, b.z, b.w};
    __half h[8], l[8];
#pragma unroll
    for (int j = 0; j < 8; j++) {
        h[j] = __float2half_rn(v[j]);
        l[j] = __float2half_rn(v[j] - __half2float(h[j]));
    }
    *(uint4*)&g_Xh[i] = *(const uint4*)h;
    *(uint4*)&g_Xl[i] = *(const uint4*)l;
}

// ---------------- fused prepA: A->fp16, denom column-sums, bias = A@cb ----------------
__global__ __launch_bounds__(256) void prepA_kernel(const float* __restrict__ Ag,
                                                    const float* __restrict__ cb) {
    __shared__ float cb_s[KK*KK];
    __shared__ float A_s[32][65];
    __shared__ float dsum[KK];
    int tid = threadIdx.x, lane = tid & 31;
    {
        const float4* cb4 = (const float4*)cb;
        float4* cbs4 = (float4*)cb_s;
        for (int i = tid; i < KK*KK/4; i += 256) cbs4[i] = cb4[i];
    }
    if (tid < KK) dsum[tid] = 0.0f;
    __syncthreads();

    size_t i = ((size_t)blockIdx.x * 256 + tid) * 8;
    float4 a = *(const float4*)(Ag + i);
    float4 b = *(const float4*)(Ag + i + 4);
    float v[8] = {a.x, a.y, a.z, a.w, b.x, b.y, b.z, b.w};
    __half h[8];
#pragma unroll
    for (int j = 0; j < 8; j++) h[j] = __float2half_rn(v[j]);
    *(uint4*)&g_Ah[i] = *(const uint4*)h;
    int tt = tid >> 3, cg = tid & 7;
#pragma unroll
    for (int j = 0; j < 8; j++) A_s[tt][cg * 8 + j] = v[j];
#pragma unroll
    for (int j = 0; j < 8; j++) {
        v[j] += __shfl_down_sync(0xffffffffu, v[j], 16);
        v[j] += __shfl_down_sync(0xffffffffu, v[j], 8);
    }
    if (lane < 8) {
        int k0 = (tid & 7) * 8;
#pragma unroll
        for (int j = 0; j < 8; j++) atomicAdd(&dsum[k0 + j], v[j]);
    }
    __syncthreads();

    {
        float acc[8];
#pragma unroll
        for (int j = 0; j < 8; j++) acc[j] = 0.0f;
#pragma unroll 8
        for (int k = 0; k < KK; k++) {
            float av = A_s[tt][k];
            const float4* cbr = (const float4*)(cb_s + k * KK + cg * 8);
            float4 c0 = cbr[0], c1 = cbr[1];
            acc[0] += av * c0.x; acc[1] += av * c0.y;
            acc[2] += av * c0.z; acc[3] += av * c0.w;
            acc[4] += av * c1.x; acc[5] += av * c1.y;
            acc[6] += av * c1.z; acc[7] += av * c1.w;
        }
        size_t tok = (size_t)blockIdx.x * 32 + tt;
        float4* dst = (float4*)(g_bias + tok * KK + cg * 8);
        dst[0] = make_float4(acc[0], acc[1], acc[2], acc[3]);
        dst[1] = make_float4(acc[4], acc[5], acc[6], acc[7]);
    }
    if (tid < KK) {
        int b_ = blockIdx.x >> 9;
        atomicAdd(&g_denom[b_ * KK + tid], dsum[tid]);
    }
}

// ---------------- transposed fp16 hi/lo weights ----------------
__global__ __launch_bounds__(256) void prepW_kernel(const float* __restrict__ wqkv,
                                                    const float* __restrict__ wproj) {
    int n = blockIdx.x, k = threadIdx.x;
    float wq = wqkv[k * (3*CC) + n];
    float wp = wproj[k * CC + n];
    __half qh = __float2half_rn(wq);
    __half ph = __float2half_rn(wp);
    int o = n * CC + k;
    g_Wqt_hi[o] = qh;
    g_Wqt_lo[o] = __float2half_rn(wq - __half2float(qh));
    g_Wpt_hi[o] = ph;
    g_Wpt_lo[o] = __float2half_rn(wp - __half2float(ph));
}

// ---------------- tensor-core pooling (unchanged) ----------------
#define PX_ST 264
#define PA_ST 72
#define PX_SIZE (64*PX_ST)
#define PA_SIZE (64*PA_ST)
#define POOL_SMEM ((3*PX_SIZE + 3*PA_SIZE)*2)
__global__ __launch_bounds__(256, 1) void pool_tc_kernel() {
    extern __shared__ __half ps[];
    uint32_t sb = smem_u32(ps);
    int tid = threadIdx.x, lane = tid & 31, w = tid >> 5;
    int wm = w >> 2, wn = w & 3;
    int b = blockIdx.x >> 5;
    int nbase = (blockIdx.x & 31) * 512;
    const __half* Asrc[2] = {g_Ah, g_Ah};
    const __half* Xsrc[2] = {g_Xh, g_Xl};

    float acc[2][8][4];
#pragma unroll
    for (int i = 0; i < 2; i++)
#pragma unroll
        for (int j = 0; j < 8; j++)
#pragma unroll
            for (int r = 0; r < 4; r++) acc[i][j][r] = 0.0f;

    auto issue = [&](int c) {
        int s = c >> 3, kc_ = c & 7, buf = c % 3;
        size_t grow0 = (size_t)b * NN + nbase + kc_ * 64;
#pragma unroll
        for (int i = 0; i < 8; i++) {
            int idx = tid + i * 256;
            int row = idx >> 5, ch = idx & 31;
            CP16(sb + (uint32_t)(buf * PX_SIZE + row * PX_ST + ch * 8) * 2,
                 Xsrc[s] + (grow0 + row) * CC + ch * 8);
        }
#pragma unroll
        for (int i = 0; i < 2; i++) {
            int idx = tid + i * 256;
            int row = idx >> 3, ch = idx & 7;
            CP16(sb + (uint32_t)(3 * PX_SIZE + buf * PA_SIZE + row * PA_ST + ch * 8) * 2,
                 Asrc[s] + (grow0 + row) * KK + ch * 8);
        }
        CPCOMMIT();
    };

    issue(0); issue(1);
#pragma unroll 1
    for (int c = 0; c < 16; c++) {
        if (c < 14) { CPWAIT(1); } else { CPWAIT(0); }
        __syncthreads();
        if (c + 2 < 16) issue(c + 2);
        int buf = c % 3;
        uint32_t xb = sb + (uint32_t)(buf * PX_SIZE) * 2;
        uint32_t ab = sb + (uint32_t)(3 * PX_SIZE + buf * PA_SIZE) * 2;
#pragma unroll
        for (int kt = 0; kt < 4; kt++) {
            uint32_t af[2][4];
#pragma unroll
            for (int mt = 0; mt < 2; mt++) {
                uint32_t r[4];
                ldsm_x4_t(r, ab + (uint32_t)((kt * 16 + (lane & 15)) * PA_ST +
                                             wm * 32 + mt * 16 + (lane >> 4) * 8) * 2);
                af[mt][0] = r[0]; af[mt][1] = r[2]; af[mt][2] = r[1]; af[mt][3] = r[3];
            }
#pragma unroll
            for (int nb = 0; nb < 4; nb++) {
                uint32_t bfr[4];
                ldsm_x4_t(bfr, xb + (uint32_t)((kt * 16 + (lane & 15)) * PX_ST +
                                               wn * 64 + nb * 16 + (lane >> 4) * 8) * 2);
#pragma unroll
                for (int mt = 0; mt < 2; mt++) {
                    mma_fp16(acc[mt][nb*2],   af[mt], bfr[0], bfr[1]);
                    mma_fp16(acc[mt][nb*2+1], af[mt], bfr[2], bfr[3]);
                }
            }
        }
    }
#pragma unroll
    for (int mt = 0; mt < 2; mt++)
#pragma unroll
        for (int nt = 0; nt < 8; nt++) {
            int cl = wm * 32 + mt * 16 + (lane >> 2);
            int col = wn * 64 + nt * 8 + 2 * (lane & 3);
            float* d0 = &g_S[(b * KK + cl) * CC + col];
            atomicAdd(d0,     acc[mt][nt][0]);
            atomicAdd(d0 + 1, acc[mt][nt][1]);
            float* d1 = &g_S[(b * KK + cl + 8) * CC + col];
            atomicAdd(d1,     acc[mt][nt][2]);
            atomicAdd(d1 + 1, acc[mt][nt][3]);
        }
}

// ---------------- kc/vc from S -> scaled fp16 2-term splits ----------------
__global__ __launch_bounds__(256) void kcvc_kernel(const float* __restrict__ wqkv) {
    int bk = blockIdx.x;
    int b = bk >> 6;
    int k = bk & 63;
    int t = threadIdx.x;
    __shared__ float s_row[CC];
    s_row[t] = g_S[bk * CC + t];
    __syncthreads();
    float inv = 1.0f / (g_denom[bk] + 1e-8f);
    float ak = 0.0f, av = 0.0f;
#pragma unroll 8
    for (int c = 0; c < CC; c++) {
        float s = s_row[c];
        ak += s * wqkv[c * (3*CC) + CC  + t];
        av += s * wqkv[c * (3*CC) + 2*CC + t];
    }
    int h = t >> 5, dd = t & 31;
    const float SC = 0.17677669529663689f;
    float kcv = ak * inv * SC;
    float vcv = av * inv;
    size_t ok = ((size_t)(b * HH + h) * KK + k) * DD + dd;
    size_t ov = ((size_t)(b * HH + h) * DD + dd) * KK + k;
    __half kh = __float2half_rn(kcv);
    __half vh = __float2half_rn(vcv);
    g_kchi[ok] = kh;  g_kclo[ok] = __float2half_rn(kcv - __half2float(kh));
    g_vcThi[ov] = vh; g_vcTlo[ov] = __float2half_rn(vcv - __half2float(vh));
}

// ---------------- HMMA fp16 2-term GEMM (unchanged) ----------------
#define AST 40
#define TILE_ELE (128 * AST)
#define STAGE_ELE (3 * TILE_ELE)
#define GEMM_SMEM_BYTES (3 * STAGE_ELE * 2)
__global__ __launch_bounds__(256, 2) void gemm_fp16x2_mma(
    const __half* __restrict__ Am, int a_planar,
    const __half* __restrict__ Whi, const __half* __restrict__ Wlo,
    const float* __restrict__ bias, float* __restrict__ Cout,
    __half* __restrict__ Oh) {
    extern __shared__ __half smemh[];
    uint32_t s_base = smem_u32(smemh);

    int tid = threadIdx.x;
    int lane = tid & 31, w = tid >> 5;
    int wr = w >> 2, wc = w & 3;
    size_t mbase = (size_t)blockIdx.x * 128;
    int nbase = blockIdx.y * 128;

    int ldrow = tid >> 1;
    int ldw0  = (tid & 1) * 2;

    float acc[4][4][4];
#pragma unroll
    for (int i = 0; i < 4; i++)
#pragma unroll
        for (int j = 0; j < 4; j++)
#pragma unroll
            for (int r = 0; r < 4; r++) acc[i][j][r] = 0.0f;

    auto issue = [&](int c) {
        int ko = c * 32;
        uint32_t sa = s_base + (uint32_t)((c % 3) * STAGE_ELE) * 2;
        const __half* Abase = a_planar
            ? Am + ((size_t)c * BNTOT + mbase + ldrow) * 32
            : Am + (mbase + ldrow) * CC + ko;
#pragma unroll
        for (int j = 0; j < 2; j++) {
            int cw = ldw0 + j;
            uint32_t d = (uint32_t)(ldrow * AST + cw * 8) * 2;
            CP16(sa + d,                    Abase + cw * 8);
            CP16(sa + d + TILE_ELE * 2,     Whi + (size_t)(nbase + ldrow) * CC + ko + cw * 8);
            CP16(sa + d + 2 * TILE_ELE * 2, Wlo + (size_t)(nbase + ldrow) * CC + ko + cw * 8);
        }
        CPCOMMIT();
    };

    int arow = (lane & 7) + 8 * ((lane >> 3) & 1);
    int akw  = (lane >> 4) * 8;
    int brow = (lane & 7) + 8 * ((lane >> 4) & 1);
    int bkw  = ((lane >> 3) & 1) * 8;

    auto compute = [&](int stage) {
        uint32_t sa  = s_base + (uint32_t)(stage * STAGE_ELE) * 2;
        uint32_t sbh = sa + (uint32_t)TILE_ELE * 2;
        uint32_t sbl = sa + (uint32_t)(2 * TILE_ELE) * 2;
#pragma unroll
        for (int ks = 0; ks < 32; ks += 16) {
            uint32_t afr[4][4];
#pragma unroll
            for (int mt = 0; mt < 4; mt++)
                ldsm_x4(afr[mt], sa + (uint32_t)(((wr * 64 + mt * 16 + arow) * AST) + ks + akw) * 2);
            uint32_t bh[2][4], bl[2][4];
#pragma unroll
            for (int nt2 = 0; nt2 < 2; nt2++) {
                uint32_t off = (uint32_t)(((wc * 32 + nt2 * 16 + brow) * AST) + ks + bkw) * 2;
                ldsm_x4(bh[nt2], sbh + off);
                ldsm_x4(bl[nt2], sbl + off);
            }
#pragma unroll
            for (int mt = 0; mt < 4; mt++)
#pragma unroll
                for (int nt = 0; nt < 4; nt++) {
                    mma_fp16(acc[mt][nt], afr[mt],
                             bh[nt >> 1][(nt & 1) * 2], bh[nt >> 1][(nt & 1) * 2 + 1]);
                    mma_fp16(acc[mt][nt], afr[mt],
                             bl[nt >> 1][(nt & 1) * 2], bl[nt >> 1][(nt & 1) * 2 + 1]);
                }
        }
    };

    issue(0);
    issue(1);
#pragma unroll 1
    for (int c = 0; c < 8; c++) {
        if (c < 6) { CPWAIT(1); } else { CPWAIT(0); }
        __syncthreads();
        if (c + 2 < 8) issue(c + 2);
        compute(c % 3);
    }

    int g = lane >> 2, ti = lane & 3;
#pragma unroll
    for (int mt = 0; mt < 4; mt++) {
#pragma unroll
        for (int nt = 0; nt < 4; nt++) {
            size_t row = mbase + wr * 64 + mt * 16 + g;
            int col = nbase + wc * 32 + nt * 8 + ti * 2;
            if (Cout) {
                float bx = 0.0f, by = 0.0f;
                if (bias) { bx = bias[col]; by = bias[col + 1]; }
                float2 v0, v1;
                v0.x = acc[mt][nt][0] + bx; v0.y = acc[mt][nt][1] + by;
                v1.x = acc[mt][nt][2] + bx; v1.y = acc[mt][nt][3] + by;
                *(float2*)&Cout[row * CC + col] = v0;
                *(float2*)&Cout[(row + 8) * CC + col] = v1;
            } else {
                int hh = col >> 5, dd0 = col & 31;
                size_t o0 = ((size_t)hh * BNTOT + row) * 32 + dd0;
                size_t o1 = ((size_t)hh * BNTOT + row + 8) * 32 + dd0;
                *(uint32_t*)&Oh[o0] = pack_h2(acc[mt][nt][0], acc[mt][nt][1]);
                *(uint32_t*)&Oh[o1] = pack_h2(acc[mt][nt][2], acc[mt][nt][3]);
            }
        }
    }
}

// ---------------- tensor-core attention: fp16 datapath + smem-cached bias ----------------
#define ATT_BUF_BYTES 19456
#define ATT_BIAS_OFF  (2 * ATT_BUF_BYTES)              // 38912 B
#define ATT_SMEM_BYTES (ATT_BIAS_OFF + 128 * 65 * 4)   // + 33280 = 72192 B
__global__ __launch_bounds__(256, 2) void attn_tc_kernel() {
    extern __shared__ __half smn[];
    uint32_t sb = smem_u32(smn);
    float* bias_s = (float*)((char*)smn + ATT_BIAS_OFF);
    int tid = threadIdx.x, lane = tid & 31, w = tid >> 5;
    size_t tok0 = (size_t)blockIdx.x * 128;
    int b = blockIdx.x >> 7;
    int r = lane >> 2, c = lane & 3;
    size_t trow0 = tok0 + (size_t)w * 16 + r;
    size_t trow1 = trow0 + 8;

    const uint32_t KHI = 0, KLO = 5120, VHI = 10240, VLO = 14848;

    auto issue_head = [&](int h) {
        uint32_t bo = (uint32_t)(h & 1) * ATT_BUF_BYTES;
        {
            int rr = tid >> 2, cc = tid & 3;
            size_t src = ((size_t)(b * HH + h) * KK + rr) * DD + cc * 8;
            uint32_t d = (uint32_t)(rr * 40 + cc * 8) * 2;
            CP16(sb + bo + KHI + d, g_kchi + src);
            CP16(sb + bo + KLO + d, g_kclo + src);
        }
        {
            int rr = tid >> 3, cc = tid & 7;
            size_t src = ((size_t)(b * HH + h) * DD + rr) * KK + cc * 8;
            uint32_t d = (uint32_t)(rr * 72 + cc * 8) * 2;
            CP16(sb + bo + VHI + d, g_vcThi + src);
            CP16(sb + bo + VLO + d, g_vcTlo + src);
        }
        CPCOMMIT();
    };
    issue_head(0);

    // stage bias rows into smem once (padded stride 65; scalar stores — alignment-safe)
    for (int i = tid; i < 128 * 32; i += 256) {
        int row = i >> 5, col2 = (i & 31) * 2;
        float2 bv = *(const float2*)(g_bias + (tok0 + row) * KK + col2);
        bias_s[row * 65 + col2]     = bv.x;
        bias_s[row * 65 + col2 + 1] = bv.y;
    }

    int brow = (lane & 7) + 8 * ((lane >> 4) & 1);
    int bkw  = ((lane >> 3) & 1) * 8;
    int lrow0 = w * 16 + r;

#pragma unroll 1
    for (int h = 0; h < HH; h++) {
        CPWAIT(0);
        __syncthreads();
        if (h + 1 < HH) issue_head(h + 1);
        uint32_t bo = (uint32_t)(h & 1) * ATT_BUF_BYTES;

        const __half* q_base = g_qh + (size_t)h * BNTOT * 32;
        uint32_t q[2][4];
#pragma unroll
        for (int ks = 0; ks < 2; ks++) {
            int col = ks * 16 + c * 2;
            q[ks][0] = *(const uint32_t*)(q_base + trow0 * 32 + col);
            q[ks][1] = *(const uint32_t*)(q_base + trow1 * 32 + col);
            q[ks][2] = *(const uint32_t*)(q_base + trow0 * 32 + col + 8);
            q[ks][3] = *(const uint32_t*)(q_base + trow1 * 32 + col + 8);
        }

        float L[8][4];
#pragma unroll
        for (int t = 0; t < 8; t++) {
            // scalar loads: stride-65 rows are only 4B-aligned (float2 here crashed R14)
            L[t][0] = bias_s[lrow0 * 65 + t * 8 + c * 2];
            L[t][1] = bias_s[lrow0 * 65 + t * 8 + c * 2 + 1];
            L[t][2] = bias_s[(lrow0 + 8) * 65 + t * 8 + c * 2];
            L[t][3] = bias_s[(lrow0 + 8) * 65 + t * 8 + c * 2 + 1];
        }
#pragma unroll
        for (int g2 = 0; g2 < 4; g2++) {
#pragma unroll
            for (int ks = 0; ks < 2; ks++) {
                uint32_t bh[4], bl[4];
                uint32_t ad = (uint32_t)((g2 * 16 + brow) * 40 + ks * 16 + bkw) * 2;
                ldsm_x4(bh, sb + bo + KHI + ad);
                ldsm_x4(bl, sb + bo + KLO + ad);
                mma_fp16(L[2*g2],   q[ks], bh[0], bh[1]);
                mma_fp16(L[2*g2],   q[ks], bl[0], bl[1]);
                mma_fp16(L[2*g2+1], q[ks], bh[2], bh[3]);
                mma_fp16(L[2*g2+1], q[ks], bl[2], bl[3]);
            }
        }

        float m0 = -1e30f, m1 = -1e30f;
#pragma unroll
        for (int t = 0; t < 8; t++) {
            m0 = fmaxf(m0, fmaxf(L[t][0], L[t][1]));
            m1 = fmaxf(m1, fmaxf(L[t][2], L[t][3]));
        }
        m0 = fmaxf(m0, __shfl_xor_sync(0xffffffffu, m0, 1));
        m0 = fmaxf(m0, __shfl_xor_sync(0xffffffffu, m0, 2));
        m1 = fmaxf(m1, __shfl_xor_sync(0xffffffffu, m1, 1));
        m1 = fmaxf(m1, __shfl_xor_sync(0xffffffffu, m1, 2));
        float s0 = 0.0f, s1 = 0.0f;
#pragma unroll
        for (int t = 0; t < 8; t++) {
            L[t][0] = __expf(L[t][0] - m0); s0 += L[t][0];
            L[t][1] = __expf(L[t][1] - m0); s0 += L[t][1];
            L[t][2] = __expf(L[t][2] - m1); s1 += L[t][2];
            L[t][3] = __expf(L[t][3] - m1); s1 += L[t][3];
        }
        s0 += __shfl_xor_sync(0xffffffffu, s0, 1);
        s0 += __shfl_xor_sync(0xffffffffu, s0, 2);
        s1 += __shfl_xor_sync(0xffffffffu, s1, 1);
        s1 += __shfl_xor_sync(0xffffffffu, s1, 2);
        float inv0 = 1.0f / s0, inv1 = 1.0f / s1;

        float O[4][4];
#pragma unroll
        for (int t = 0; t < 4; t++)
#pragma unroll
            for (int v = 0; v < 4; v++) O[t][v] = 0.0f;
#pragma unroll
        for (int kc_ = 0; kc_ < 4; kc_++) {
            uint32_t p[4];
            p[0] = pack_h2(L[2*kc_][0] * inv0,   L[2*kc_][1] * inv0);
            p[1] = pack_h2(L[2*kc_][2] * inv1,   L[2*kc_][3] * inv1);
            p[2] = pack_h2(L[2*kc_+1][0] * inv0, L[2*kc_+1][1] * inv0);
            p[3] = pack_h2(L[2*kc_+1][2] * inv1, L[2*kc_+1][3] * inv1);
#pragma unroll
            for (int g2 = 0; g2 < 2; g2++) {
                uint32_t bh[4], bl[4];
                uint32_t ad = (uint32_t)((g2 * 16 + brow) * 72 + kc_ * 16 + bkw) * 2;
                ldsm_x4(bh, sb + bo + VHI + ad);
                ldsm_x4(bl, sb + bo + VLO + ad);
                mma_fp16(O[2*g2],   p, bh[0], bh[1]);
                mma_fp16(O[2*g2],   p, bl[0], bl[1]);
                mma_fp16(O[2*g2+1], p, bh[2], bh[3]);
                mma_fp16(O[2*g2+1], p, bl[2], bl[3]);
            }
        }

        __half* xh_base = g_xh + (size_t)h * BNTOT * 32;
#pragma unroll
        for (int nt = 0; nt < 4; nt++) {
            int col = nt * 8 + c * 2;
            *(uint32_t*)&xh_base[trow0 * 32 + col] = pack_h2(O[nt][0], O[nt][1]);
            *(uint32_t*)&xh_base[trow1 * 32 + col] = pack_h2(O[nt][2], O[nt][3]);
        }
    }
}

// ---------------- launcher ----------------
extern "C" void kernel_launch(void* const* d_in, const int* in_sizes, int n_in,
                              void* d_out, int out_size) {
    const float* X     = (const float*)d_in[0];
    const float* Ag    = (const float*)d_in[1];
    const float* wqkv  = (const float*)d_in[2];
    const float* wproj = (const float*)d_in[3];
    const float* bproj = (const float*)d_in[4];
    const float* cb    = (const float*)d_in[5];
    float* out = (float*)d_out;

    __half *pXh, *pxh, *pqh, *pWqh, *pWql, *pWph, *pWpl;
    float *pS, *pden;
    cudaGetSymbolAddress((void**)&pXh, g_Xh);
    cudaGetSymbolAddress((void**)&pxh, g_xh);
    cudaGetSymbolAddress((void**)&pqh, g_qh);
    cudaGetSymbolAddress((void**)&pWqh, g_Wqt_hi);
    cudaGetSymbolAddress((void**)&pWql, g_Wqt_lo);
    cudaGetSymbolAddress((void**)&pWph, g_Wpt_hi);
    cudaGetSymbolAddress((void**)&pWpl, g_Wpt_lo);
    cudaGetSymbolAddress((void**)&pS, g_S);
    cudaGetSymbolAddress((void**)&pden, g_denom);

    cudaFuncSetAttribute(gemm_fp16x2_mma,
                         cudaFuncAttributeMaxDynamicSharedMemorySize, GEMM_SMEM_BYTES);
    cudaFuncSetAttribute(pool_tc_kernel,
                         cudaFuncAttributeMaxDynamicSharedMemorySize, POOL_SMEM);
    cudaFuncSetAttribute(attn_tc_kernel,
                         cudaFuncAttributeMaxDynamicSharedMemorySize, ATT_SMEM_BYTES);

    cudaMemsetAsync(pS, 0, sizeof(float) * BB * KK * CC);
    cudaMemsetAsync(pden, 0, sizeof(float) * BB * KK);
    convertX_kernel<<<(BNTOT*CC) / (256*8), 256>>>(X);
    prepW_kernel<<<CC, 256>>>(wqkv, wproj);
    {   // Q = X @ Wq, single fp16 planar output
        dim3 grid(BNTOT / 128, CC / 128);
        gemm_fp16x2_mma<<<grid, 256, GEMM_SMEM_BYTES>>>(pXh, 0, pWqh, pWql,
                                                        nullptr, nullptr, pqh);
    }
    prepA_kernel<<<(BNTOT*KK) / (256*8), 256>>>(Ag, cb);
    pool_tc_kernel<<<BB * 32, 256, POOL_SMEM>>>();
    kcvc_kernel<<<BB * KK, 256>>>(wqkv);
    attn_tc_kernel<<<BNTOT / 128, 256, ATT_SMEM_BYTES>>>();
    {   // out = x @ Wproj + b
        dim3 grid(BNTOT / 128, CC / 128);
        gemm_fp16x2_mma<<<grid, 256, GEMM_SMEM_BYTES>>>(pxh, 1, pWph, pWpl,
                                                        bproj, out, nullptr);
    }
}

// round 16
// speedup vs baseline: 1.1057x; 1.1057x over previous
#include <cuda_runtime.h>
#include <cuda_bf16.h>
#include <cuda_fp16.h>
#include <cstdint>
#include <math.h>

#define BB 4
#define NN 16384
#define CC 256
#define HH 8
#define KK 64
#define DD 32
#define BNTOT (BB*NN)

// ---------------- scratch ----------------
__device__ float g_S[BB*KK*CC];
__device__ float g_denom[BB*KK];
__device__ float g_bias[BNTOT*KK];
__device__ __half g_Xh[BNTOT*CC], g_Xl[BNTOT*CC];
__device__ __half g_Ah[BNTOT*KK];
__device__ __half g_xh[BNTOT*CC];                 // PLANAR [h][n][32] fp16
__device__ __half g_qh[BNTOT*CC];                 // PLANAR [h][n][32] fp16
__device__ __half g_Wqt_hi[CC*CC], g_Wqt_lo[CC*CC];
__device__ __half g_Wpt_hi[CC*CC], g_Wpt_lo[CC*CC];
__device__ __half g_kchi[BB*HH*KK*DD], g_kclo[BB*HH*KK*DD];
__device__ __half g_vcThi[BB*HH*DD*KK], g_vcTlo[BB*HH*DD*KK];

// ---------------- helpers ----------------
__device__ __forceinline__ uint32_t smem_u32(const void* p) {
    uint32_t a;
    asm("{ .reg .u64 t; cvta.to.shared.u64 t, %1; cvt.u32.u64 %0, t; }" : "=r"(a) : "l"(p));
    return a;
}
#define CP16(dst, src) \
    asm volatile("cp.async.cg.shared.global [%0], [%1], 16;" :: "r"(dst), "l"(src))
#define CPCOMMIT() asm volatile("cp.async.commit_group;" ::: "memory")
#define CPWAIT(n)  asm volatile("cp.async.wait_group %0;" :: "n"(n) : "memory")

__device__ __forceinline__ void ldsm_x4(uint32_t* r, uint32_t addr) {
    asm volatile("ldmatrix.sync.aligned.m8n8.x4.shared.b16 {%0,%1,%2,%3}, [%4];"
                 : "=r"(r[0]), "=r"(r[1]), "=r"(r[2]), "=r"(r[3]) : "r"(addr));
}
__device__ __forceinline__ void ldsm_x4_t(uint32_t* r, uint32_t addr) {
    asm volatile("ldmatrix.sync.aligned.m8n8.x4.trans.shared.b16 {%0,%1,%2,%3}, [%4];"
                 : "=r"(r[0]), "=r"(r[1]), "=r"(r[2]), "=r"(r[3]) : "r"(addr));
}
__device__ __forceinline__ void mma_fp16(float* d, const uint32_t* a,
                                         uint32_t b0, uint32_t b1) {
    asm volatile(
        "mma.sync.aligned.m16n8k16.row.col.f32.f16.f16.f32 "
        "{%0,%1,%2,%3}, {%4,%5,%6,%7}, {%8,%9}, {%0,%1,%2,%3};"
        : "+f"(d[0]), "+f"(d[1]), "+f"(d[2]), "+f"(d[3])
        : "r"(a[0]), "r"(a[1]), "r"(a[2]), "r"(a[3]), "r"(b0), "r"(b1));
}
__device__ __forceinline__ uint32_t pack_h2(float a, float b) {
    __half2 h = __floats2half2_rn(a, b);
    return *(uint32_t*)&h;
}

// ---------------- fp16 split of X ----------------
__global__ __launch_bounds__(256) void convertX_kernel(const float* __restrict__ X) {
    size_t i = ((size_t)blockIdx.x * 256 + threadIdx.x) * 8;
    float4 a = *(const float4*)(X + i);
    float4 b = *(const float4*)(X + i + 4);
    float v[8] = {a.x, a.y, a.z, a.w, b.x, b.y, b.z, b.w};
    __half h[8], l[8];
#pragma unroll
    for (int j = 0; j < 8; j++) {
        h[j] = __float2half_rn(v[j]);
        l[j] = __float2half_rn(v[j] - __half2float(h[j]));
    }
    *(uint4*)&g_Xh[i] = *(const uint4*)h;
    *(uint4*)&g_Xl[i] = *(const uint4*)l;
}

// ---------------- convertA + fused denom (R13 version) ----------------
__global__ __launch_bounds__(256) void convertA_kernel(const float* __restrict__ Ag) {
    __shared__ float dsum[KK];
    int tid = threadIdx.x, lane = tid & 31;
    if (tid < KK) dsum[tid] = 0.0f;
    __syncthreads();
    size_t i = ((size_t)blockIdx.x * 256 + tid) * 8;
    float4 a = *(const float4*)(Ag + i);
    float4 b = *(const float4*)(Ag + i + 4);
    float v[8] = {a.x, a.y, a.z, a.w, b.x, b.y, b.z, b.w};
    __half h[8];
#pragma unroll
    for (int j = 0; j < 8; j++) h[j] = __float2half_rn(v[j]);
    *(uint4*)&g_Ah[i] = *(const uint4*)h;
#pragma unroll
    for (int j = 0; j < 8; j++) {
        v[j] += __shfl_down_sync(0xffffffffu, v[j], 16);
        v[j] += __shfl_down_sync(0xffffffffu, v[j], 8);
    }
    if (lane < 8) {
        int k0 = (tid & 7) * 8;
#pragma unroll
        for (int j = 0; j < 8; j++) atomicAdd(&dsum[k0 + j], v[j]);
    }
    __syncthreads();
    int b_ = blockIdx.x >> 9;
    if (tid < KK) atomicAdd(&g_denom[b_ * KK + tid], dsum[tid]);
}

// ---------------- bias = A @ cluster_bias (R13 register-accumulating version) --------
__global__ __launch_bounds__(256) void bias_kernel(const float* __restrict__ Ag,
                                                   const float* __restrict__ cb) {
    __shared__ float cb_s[KK*KK];
    int tid = threadIdx.x;
    {
        const float4* cb4 = (const float4*)cb;
        float4* cbs4 = (float4*)cb_s;
        for (int i = tid; i < KK*KK/4; i += 256) cbs4[i] = cb4[i];
    }
    __syncthreads();
    size_t n = (size_t)blockIdx.x * 256 + tid;
    float biasr[64];
#pragma unroll
    for (int l = 0; l < 64; l++) biasr[l] = 0.0f;
    const float4* arow = (const float4*)(Ag + n * KK);
#pragma unroll
    for (int k4 = 0; k4 < 16; k4++) {
        float4 a4 = arow[k4];
        float avv[4] = {a4.x, a4.y, a4.z, a4.w};
#pragma unroll
        for (int kk = 0; kk < 4; kk++) {
            const float4* cbr = (const float4*)(cb_s + (k4 * 4 + kk) * 64);
#pragma unroll
            for (int l4 = 0; l4 < 16; l4++) {
                float4 c4 = cbr[l4];
                biasr[l4*4+0] += avv[kk] * c4.x;
                biasr[l4*4+1] += avv[kk] * c4.y;
                biasr[l4*4+2] += avv[kk] * c4.z;
                biasr[l4*4+3] += avv[kk] * c4.w;
            }
        }
    }
    float4* dst = (float4*)(g_bias + n * KK);
#pragma unroll
    for (int l4 = 0; l4 < 16; l4++)
        dst[l4] = make_float4(biasr[l4*4], biasr[l4*4+1], biasr[l4*4+2], biasr[l4*4+3]);
}

// ---------------- transposed fp16 hi/lo weights ----------------
__global__ __launch_bounds__(256) void prepW_kernel(const float* __restrict__ wqkv,
                                                    const float* __restrict__ wproj) {
    int n = blockIdx.x, k = threadIdx.x;
    float wq = wqkv[k * (3*CC) + n];
    float wp = wproj[k * CC + n];
    __half qh = __float2half_rn(wq);
    __half ph = __float2half_rn(wp);
    int o = n * CC + k;
    g_Wqt_hi[o] = qh;
    g_Wqt_lo[o] = __float2half_rn(wq - __half2float(qh));
    g_Wpt_hi[o] = ph;
    g_Wpt_lo[o] = __float2half_rn(wp - __half2float(ph));
}

// ---------------- tensor-core pooling (unchanged) ----------------
#define PX_ST 264
#define PA_ST 72
#define PX_SIZE (64*PX_ST)
#define PA_SIZE (64*PA_ST)
#define POOL_SMEM ((3*PX_SIZE + 3*PA_SIZE)*2)
__global__ __launch_bounds__(256, 1) void pool_tc_kernel() {
    extern __shared__ __half ps[];
    uint32_t sb = smem_u32(ps);
    int tid = threadIdx.x, lane = tid & 31, w = tid >> 5;
    int wm = w >> 2, wn = w & 3;
    int b = blockIdx.x >> 5;
    int nbase = (blockIdx.x & 31) * 512;
    const __half* Asrc[2] = {g_Ah, g_Ah};
    const __half* Xsrc[2] = {g_Xh, g_Xl};

    float acc[2][8][4];
#pragma unroll
    for (int i = 0; i < 2; i++)
#pragma unroll
        for (int j = 0; j < 8; j++)
#pragma unroll
            for (int r = 0; r < 4; r++) acc[i][j][r] = 0.0f;

    auto issue = [&](int c) {
        int s = c >> 3, kc_ = c & 7, buf = c % 3;
        size_t grow0 = (size_t)b * NN + nbase + kc_ * 64;
#pragma unroll
        for (int i = 0; i < 8; i++) {
            int idx = tid + i * 256;
            int row = idx >> 5, ch = idx & 31;
            CP16(sb + (uint32_t)(buf * PX_SIZE + row * PX_ST + ch * 8) * 2,
                 Xsrc[s] + (grow0 + row) * CC + ch * 8);
        }
#pragma unroll
        for (int i = 0; i < 2; i++) {
            int idx = tid + i * 256;
            int row = idx >> 3, ch = idx & 7;
            CP16(sb + (uint32_t)(3 * PX_SIZE + buf * PA_SIZE + row * PA_ST + ch * 8) * 2,
                 Asrc[s] + (grow0 + row) * KK + ch * 8);
        }
        CPCOMMIT();
    };

    issue(0); issue(1);
#pragma unroll 1
    for (int c = 0; c < 16; c++) {
        if (c < 14) { CPWAIT(1); } else { CPWAIT(0); }
        __syncthreads();
        if (c + 2 < 16) issue(c + 2);
        int buf = c % 3;
        uint32_t xb = sb + (uint32_t)(buf * PX_SIZE) * 2;
        uint32_t ab = sb + (uint32_t)(3 * PX_SIZE + buf * PA_SIZE) * 2;
#pragma unroll
        for (int kt = 0; kt < 4; kt++) {
            uint32_t af[2][4];
#pragma unroll
            for (int mt = 0; mt < 2; mt++) {
                uint32_t r[4];
                ldsm_x4_t(r, ab + (uint32_t)((kt * 16 + (lane & 15)) * PA_ST +
                                             wm * 32 + mt * 16 + (lane >> 4) * 8) * 2);
                af[mt][0] = r[0]; af[mt][1] = r[2]; af[mt][2] = r[1]; af[mt][3] = r[3];
            }
#pragma unroll
            for (int nb = 0; nb < 4; nb++) {
                uint32_t bfr[4];
                ldsm_x4_t(bfr, xb + (uint32_t)((kt * 16 + (lane & 15)) * PX_ST +
                                               wn * 64 + nb * 16 + (lane >> 4) * 8) * 2);
#pragma unroll
                for (int mt = 0; mt < 2; mt++) {
                    mma_fp16(acc[mt][nb*2],   af[mt], bfr[0], bfr[1]);
                    mma_fp16(acc[mt][nb*2+1], af[mt], bfr[2], bfr[3]);
                }
            }
        }
    }
#pragma unroll
    for (int mt = 0; mt < 2; mt++)
#pragma unroll
        for (int nt = 0; nt < 8; nt++) {
            int cl = wm * 32 + mt * 16 + (lane >> 2);
            int col = wn * 64 + nt * 8 + 2 * (lane & 3);
            float* d0 = &g_S[(b * KK + cl) * CC + col];
            atomicAdd(d0,     acc[mt][nt][0]);
            atomicAdd(d0 + 1, acc[mt][nt][1]);
            float* d1 = &g_S[(b * KK + cl + 8) * CC + col];
            atomicAdd(d1,     acc[mt][nt][2]);
            atomicAdd(d1 + 1, acc[mt][nt][3]);
        }
}

// ---------------- kc/vc from S -> scaled fp16 2-term splits ----------------
__global__ __launch_bounds__(256) void kcvc_kernel(const float* __restrict__ wqkv) {
    int bk = blockIdx.x;
    int b = bk >> 6;
    int k = bk & 63;
    int t = threadIdx.x;
    __shared__ float s_row[CC];
    s_row[t] = g_S[bk * CC + t];
    __syncthreads();
    float inv = 1.0f / (g_denom[bk] + 1e-8f);
    float ak = 0.0f, av = 0.0f;
#pragma unroll 8
    for (int c = 0; c < CC; c++) {
        float s = s_row[c];
        ak += s * wqkv[c * (3*CC) + CC  + t];
        av += s * wqkv[c * (3*CC) + 2*CC + t];
    }
    int h = t >> 5, dd = t & 31;
    const float SC = 0.17677669529663689f;
    float kcv = ak * inv * SC;
    float vcv = av * inv;
    size_t ok = ((size_t)(b * HH + h) * KK + k) * DD + dd;
    size_t ov = ((size_t)(b * HH + h) * DD + dd) * KK + k;
    __half kh = __float2half_rn(kcv);
    __half vh = __float2half_rn(vcv);
    g_kchi[ok] = kh;  g_kclo[ok] = __float2half_rn(kcv - __half2float(kh));
    g_vcThi[ov] = vh; g_vcTlo[ov] = __float2half_rn(vcv - __half2float(vh));
}

// ---------------- HMMA fp16 2-term GEMM (unchanged) ----------------
#define AST 40
#define TILE_ELE (128 * AST)
#define STAGE_ELE (3 * TILE_ELE)
#define GEMM_SMEM_BYTES (3 * STAGE_ELE * 2)
__global__ __launch_bounds__(256, 2) void gemm_fp16x2_mma(
    const __half* __restrict__ Am, int a_planar,
    const __half* __restrict__ Whi, const __half* __restrict__ Wlo,
    const float* __restrict__ bias, float* __restrict__ Cout,
    __half* __restrict__ Oh) {
    extern __shared__ __half smemh[];
    uint32_t s_base = smem_u32(smemh);

    int tid = threadIdx.x;
    int lane = tid & 31, w = tid >> 5;
    int wr = w >> 2, wc = w & 3;
    size_t mbase = (size_t)blockIdx.x * 128;
    int nbase = blockIdx.y * 128;

    int ldrow = tid >> 1;
    int ldw0  = (tid & 1) * 2;

    float acc[4][4][4];
#pragma unroll
    for (int i = 0; i < 4; i++)
#pragma unroll
        for (int j = 0; j < 4; j++)
#pragma unroll
            for (int r = 0; r < 4; r++) acc[i][j][r] = 0.0f;

    auto issue = [&](int c) {
        int ko = c * 32;
        uint32_t sa = s_base + (uint32_t)((c % 3) * STAGE_ELE) * 2;
        const __half* Abase = a_planar
            ? Am + ((size_t)c * BNTOT + mbase + ldrow) * 32
            : Am + (mbase + ldrow) * CC + ko;
#pragma unroll
        for (int j = 0; j < 2; j++) {
            int cw = ldw0 + j;
            uint32_t d = (uint32_t)(ldrow * AST + cw * 8) * 2;
            CP16(sa + d,                    Abase + cw * 8);
            CP16(sa + d + TILE_ELE * 2,     Whi + (size_t)(nbase + ldrow) * CC + ko + cw * 8);
            CP16(sa + d + 2 * TILE_ELE * 2, Wlo + (size_t)(nbase + ldrow) * CC + ko + cw * 8);
        }
        CPCOMMIT();
    };

    int arow = (lane & 7) + 8 * ((lane >> 3) & 1);
    int akw  = (lane >> 4) * 8;
    int brow = (lane & 7) + 8 * ((lane >> 4) & 1);
    int bkw  = ((lane >> 3) & 1) * 8;

    auto compute = [&](int stage) {
        uint32_t sa  = s_base + (uint32_t)(stage * STAGE_ELE) * 2;
        uint32_t sbh = sa + (uint32_t)TILE_ELE * 2;
        uint32_t sbl = sa + (uint32_t)(2 * TILE_ELE) * 2;
#pragma unroll
        for (int ks = 0; ks < 32; ks += 16) {
            uint32_t afr[4][4];
#pragma unroll
            for (int mt = 0; mt < 4; mt++)
                ldsm_x4(afr[mt], sa + (uint32_t)(((wr * 64 + mt * 16 + arow) * AST) + ks + akw) * 2);
            uint32_t bh[2][4], bl[2][4];
#pragma unroll
            for (int nt2 = 0; nt2 < 2; nt2++) {
                uint32_t off = (uint32_t)(((wc * 32 + nt2 * 16 + brow) * AST) + ks + bkw) * 2;
                ldsm_x4(bh[nt2], sbh + off);
                ldsm_x4(bl[nt2], sbl + off);
            }
#pragma unroll
            for (int mt = 0; mt < 4; mt++)
#pragma unroll
                for (int nt = 0; nt < 4; nt++) {
                    mma_fp16(acc[mt][nt], afr[mt],
                             bh[nt >> 1][(nt & 1) * 2], bh[nt >> 1][(nt & 1) * 2 + 1]);
                    mma_fp16(acc[mt][nt], afr[mt],
                             bl[nt >> 1][(nt & 1) * 2], bl[nt >> 1][(nt & 1) * 2 + 1]);
                }
        }
    };

    issue(0);
    issue(1);
#pragma unroll 1
    for (int c = 0; c < 8; c++) {
        if (c < 6) { CPWAIT(1); } else { CPWAIT(0); }
        __syncthreads();
        if (c + 2 < 8) issue(c + 2);
        compute(c % 3);
    }

    int g = lane >> 2, ti = lane & 3;
#pragma unroll
    for (int mt = 0; mt < 4; mt++) {
#pragma unroll
        for (int nt = 0; nt < 4; nt++) {
            size_t row = mbase + wr * 64 + mt * 16 + g;
            int col = nbase + wc * 32 + nt * 8 + ti * 2;
            if (Cout) {
                float bx = 0.0f, by = 0.0f;
                if (bias) { bx = bias[col]; by = bias[col + 1]; }
                float2 v0, v1;
                v0.x = acc[mt][nt][0] + bx; v0.y = acc[mt][nt][1] + by;
                v1.x = acc[mt][nt][2] + bx; v1.y = acc[mt][nt][3] + by;
                *(float2*)&Cout[row * CC + col] = v0;
                *(float2*)&Cout[(row + 8) * CC + col] = v1;
            } else {
                int hh = col >> 5, dd0 = col & 31;
                size_t o0 = ((size_t)hh * BNTOT + row) * 32 + dd0;
                size_t o1 = ((size_t)hh * BNTOT + row + 8) * 32 + dd0;
                *(uint32_t*)&Oh[o0] = pack_h2(acc[mt][nt][0], acc[mt][nt][1]);
                *(uint32_t*)&Oh[o1] = pack_h2(acc[mt][nt][2], acc[mt][nt][3]);
            }
        }
    }
}

// ---------------- tensor-core attention: fp16 datapath + smem-cached bias ----------------
#define ATT_BUF_BYTES 19456
#define ATT_BIAS_OFF  (2 * ATT_BUF_BYTES)
#define ATT_SMEM_BYTES (ATT_BIAS_OFF + 128 * 65 * 4)   // 72192 B
__global__ __launch_bounds__(256, 2) void attn_tc_kernel() {
    extern __shared__ __half smn[];
    uint32_t sb = smem_u32(smn);
    float* bias_s = (float*)((char*)smn + ATT_BIAS_OFF);
    int tid = threadIdx.x, lane = tid & 31, w = tid >> 5;
    size_t tok0 = (size_t)blockIdx.x * 128;
    int b = blockIdx.x >> 7;
    int r = lane >> 2, c = lane & 3;
    size_t trow0 = tok0 + (size_t)w * 16 + r;
    size_t trow1 = trow0 + 8;

    const uint32_t KHI = 0, KLO = 5120, VHI = 10240, VLO = 14848;

    auto issue_head = [&](int h) {
        uint32_t bo = (uint32_t)(h & 1) * ATT_BUF_BYTES;
        {
            int rr = tid >> 2, cc = tid & 3;
            size_t src = ((size_t)(b * HH + h) * KK + rr) * DD + cc * 8;
            uint32_t d = (uint32_t)(rr * 40 + cc * 8) * 2;
            CP16(sb + bo + KHI + d, g_kchi + src);
            CP16(sb + bo + KLO + d, g_kclo + src);
        }
        {
            int rr = tid >> 3, cc = tid & 7;
            size_t src = ((size_t)(b * HH + h) * DD + rr) * KK + cc * 8;
            uint32_t d = (uint32_t)(rr * 72 + cc * 8) * 2;
            CP16(sb + bo + VHI + d, g_vcThi + src);
            CP16(sb + bo + VLO + d, g_vcTlo + src);
        }
        CPCOMMIT();
    };
    issue_head(0);

    // stage bias rows into smem once (padded stride 65; scalar stores)
    for (int i = tid; i < 128 * 32; i += 256) {
        int row = i >> 5, col2 = (i & 31) * 2;
        float2 bv = *(const float2*)(g_bias + (tok0 + row) * KK + col2);
        bias_s[row * 65 + col2]     = bv.x;
        bias_s[row * 65 + col2 + 1] = bv.y;
    }

    int brow = (lane & 7) + 8 * ((lane >> 4) & 1);
    int bkw  = ((lane >> 3) & 1) * 8;
    int lrow0 = w * 16 + r;

#pragma unroll 1
    for (int h = 0; h < HH; h++) {
        CPWAIT(0);
        __syncthreads();
        if (h + 1 < HH) issue_head(h + 1);
        uint32_t bo = (uint32_t)(h & 1) * ATT_BUF_BYTES;

        const __half* q_base = g_qh + (size_t)h * BNTOT * 32;
        uint32_t q[2][4];
#pragma unroll
        for (int ks = 0; ks < 2; ks++) {
            int col = ks * 16 + c * 2;
            q[ks][0] = *(const uint32_t*)(q_base + trow0 * 32 + col);
            q[ks][1] = *(const uint32_t*)(q_base + trow1 * 32 + col);
            q[ks][2] = *(const uint32_t*)(q_base + trow0 * 32 + col + 8);
            q[ks][3] = *(const uint32_t*)(q_base + trow1 * 32 + col + 8);
        }

        float L[8][4];
#pragma unroll
        for (int t = 0; t < 8; t++) {
            // scalar loads (stride-65 rows are only 4B-aligned)
            L[t][0] = bias_s[lrow0 * 65 + t * 8 + c * 2];
            L[t][1] = bias_s[lrow0 * 65 + t * 8 + c * 2 + 1];
            L[t][2] = bias_s[(lrow0 + 8) * 65 + t * 8 + c * 2];
            L[t][3] = bias_s[(lrow0 + 8) * 65 + t * 8 + c * 2 + 1];
        }
#pragma unroll
        for (int g2 = 0; g2 < 4; g2++) {
#pragma unroll
            for (int ks = 0; ks < 2; ks++) {
                uint32_t bh[4], bl[4];
                uint32_t ad = (uint32_t)((g2 * 16 + brow) * 40 + ks * 16 + bkw) * 2;
                ldsm_x4(bh, sb + bo + KHI + ad);
                ldsm_x4(bl, sb + bo + KLO + ad);
                mma_fp16(L[2*g2],   q[ks], bh[0], bh[1]);
                mma_fp16(L[2*g2],   q[ks], bl[0], bl[1]);
                mma_fp16(L[2*g2+1], q[ks], bh[2], bh[3]);
                mma_fp16(L[2*g2+1], q[ks], bl[2], bl[3]);
            }
        }

        float m0 = -1e30f, m1 = -1e30f;
#pragma unroll
        for (int t = 0; t < 8; t++) {
            m0 = fmaxf(m0, fmaxf(L[t][0], L[t][1]));
            m1 = fmaxf(m1, fmaxf(L[t][2], L[t][3]));
        }
        m0 = fmaxf(m0, __shfl_xor_sync(0xffffffffu, m0, 1));
        m0 = fmaxf(m0, __shfl_xor_sync(0xffffffffu, m0, 2));
        m1 = fmaxf(m1, __shfl_xor_sync(0xffffffffu, m1, 1));
        m1 = fmaxf(m1, __shfl_xor_sync(0xffffffffu, m1, 2));
        float s0 = 0.0f, s1 = 0.0f;
#pragma unroll
        for (int t = 0; t < 8; t++) {
            L[t][0] = __expf(L[t][0] - m0); s0 += L[t][0];
            L[t][1] = __expf(L[t][1] - m0); s0 += L[t][1];
            L[t][2] = __expf(L[t][2] - m1); s1 += L[t][2];
            L[t][3] = __expf(L[t][3] - m1); s1 += L[t][3];
        }
        s0 += __shfl_xor_sync(0xffffffffu, s0, 1);
        s0 += __shfl_xor_sync(0xffffffffu, s0, 2);
        s1 += __shfl_xor_sync(0xffffffffu, s1, 1);
        s1 += __shfl_xor_sync(0xffffffffu, s1, 2);
        float inv0 = 1.0f / s0, inv1 = 1.0f / s1;

        float O[4][4];
#pragma unroll
        for (int t = 0; t < 4; t++)
#pragma unroll
            for (int v = 0; v < 4; v++) O[t][v] = 0.0f;
#pragma unroll
        for (int kc_ = 0; kc_ < 4; kc_++) {
            uint32_t p[4];
            p[0] = pack_h2(L[2*kc_][0] * inv0,   L[2*kc_][1] * inv0);
            p[1] = pack_h2(L[2*kc_][2] * inv1,   L[2*kc_][3] * inv1);
            p[2] = pack_h2(L[2*kc_+1][0] * inv0, L[2*kc_+1][1] * inv0);
            p[3] = pack_h2(L[2*kc_+1][2] * inv1, L[2*kc_+1][3] * inv1);
#pragma unroll
            for (int g2 = 0; g2 < 2; g2++) {
                uint32_t bh[4], bl[4];
                uint32_t ad = (uint32_t)((g2 * 16 + brow) * 72 + kc_ * 16 + bkw) * 2;
                ldsm_x4(bh, sb + bo + VHI + ad);
                ldsm_x4(bl, sb + bo + VLO + ad);
                mma_fp16(O[2*g2],   p, bh[0], bh[1]);
                mma_fp16(O[2*g2],   p, bl[0], bl[1]);
                mma_fp16(O[2*g2+1], p, bh[2], bh[3]);
                mma_fp16(O[2*g2+1], p, bl[2], bl[3]);
            }
        }

        __half* xh_base = g_xh + (size_t)h * BNTOT * 32;
#pragma unroll
        for (int nt = 0; nt < 4; nt++) {
            int col = nt * 8 + c * 2;
            *(uint32_t*)&xh_base[trow0 * 32 + col] = pack_h2(O[nt][0], O[nt][1]);
            *(uint32_t*)&xh_base[trow1 * 32 + col] = pack_h2(O[nt][2], O[nt][3]);
        }
    }
}

// ---------------- launcher ----------------
extern "C" void kernel_launch(void* const* d_in, const int* in_sizes, int n_in,
                              void* d_out, int out_size) {
    const float* X     = (const float*)d_in[0];
    const float* Ag    = (const float*)d_in[1];
    const float* wqkv  = (const float*)d_in[2];
    const float* wproj = (const float*)d_in[3];
    const float* bproj = (const float*)d_in[4];
    const float* cb    = (const float*)d_in[5];
    float* out = (float*)d_out;

    __half *pXh, *pxh, *pqh, *pWqh, *pWql, *pWph, *pWpl;
    float *pS, *pden;
    cudaGetSymbolAddress((void**)&pXh, g_Xh);
    cudaGetSymbolAddress((void**)&pxh, g_xh);
    cudaGetSymbolAddress((void**)&pqh, g_qh);
    cudaGetSymbolAddress((void**)&pWqh, g_Wqt_hi);
    cudaGetSymbolAddress((void**)&pWql, g_Wqt_lo);
    cudaGetSymbolAddress((void**)&pWph, g_Wpt_hi);
    cudaGetSymbolAddress((void**)&pWpl, g_Wpt_lo);
    cudaGetSymbolAddress((void**)&pS, g_S);
    cudaGetSymbolAddress((void**)&pden, g_denom);

    cudaFuncSetAttribute(gemm_fp16x2_mma,
                         cudaFuncAttributeMaxDynamicSharedMemorySize, GEMM_SMEM_BYTES);
    cudaFuncSetAttribute(pool_tc_kernel,
                         cudaFuncAttributeMaxDynamicSharedMemorySize, POOL_SMEM);
    cudaFuncSetAttribute(attn_tc_kernel,
                         cudaFuncAttributeMaxDynamicSharedMemorySize, ATT_SMEM_BYTES);

    cudaMemsetAsync(pS, 0, sizeof(float) * BB * KK * CC);
    cudaMemsetAsync(pden, 0, sizeof(float) * BB * KK);
    convertX_kernel<<<(BNTOT*CC) / (256*8), 256>>>(X);
    prepW_kernel<<<CC, 256>>>(wqkv, wproj);
    {   // Q = X @ Wq, single fp16 planar output
        dim3 grid(BNTOT / 128, CC / 128);
        gemm_fp16x2_mma<<<grid, 256, GEMM_SMEM_BYTES>>>(pXh, 0, pWqh, pWql,
                                                        nullptr, nullptr, pqh);
    }
    convertA_kernel<<<(BNTOT*KK) / (256*8), 256>>>(Ag);
    bias_kernel<<<BNTOT / 256, 256>>>(Ag, cb);
    pool_tc_kernel<<<BB * 32, 256, POOL_SMEM>>>();
    kcvc_kernel<<<BB * KK, 256>>>(wqkv);
    attn_tc_kernel<<<BNTOT / 128, 256, ATT_SMEM_BYTES>>>();
    {   // out = x @ Wproj + b
        dim3 grid(BNTOT / 128, CC / 128);
        gemm_fp16x2_mma<<<grid, 256, GEMM_SMEM_BYTES>>>(pxh, 1, pWph, pWpl,
                                                        bproj, out, nullptr);
    }
}

// round 17
// speedup vs baseline: 1.1174x; 1.0106x over previous
#include <cuda_runtime.h>
#include <cuda_bf16.h>
#include <cuda_fp16.h>
#include <cstdint>
#include <math.h>

#define BB 4
#define NN 16384
#define CC 256
#define HH 8
#define KK 64
#define DD 32
#define BNTOT (BB*NN)

// ---------------- scratch ----------------
__device__ float g_S[BB*KK*CC];
__device__ float g_denom[BB*KK];
__device__ __half g_biash[BNTOT*KK];              // bias in fp16 (halved traffic)
__device__ __half g_Xh[BNTOT*CC], g_Xl[BNTOT*CC];
__device__ __half g_Ah[BNTOT*KK];
__device__ __half g_xh[BNTOT*CC];                 // PLANAR [h][n][32] fp16
__device__ __half g_qh[BNTOT*CC];                 // PLANAR [h][n][32] fp16
__device__ __half g_Wqt_hi[CC*CC], g_Wqt_lo[CC*CC];
__device__ __half g_Wpt_hi[CC*CC], g_Wpt_lo[CC*CC];
__device__ __half g_kchi[BB*HH*KK*DD], g_kclo[BB*HH*KK*DD];
__device__ __half g_vcThi[BB*HH*DD*KK], g_vcTlo[BB*HH*DD*KK];

// ---------------- helpers ----------------
__device__ __forceinline__ uint32_t smem_u32(const void* p) {
    uint32_t a;
    asm("{ .reg .u64 t; cvta.to.shared.u64 t, %1; cvt.u32.u64 %0, t; }" : "=r"(a) : "l"(p));
    return a;
}
#define CP16(dst, src) \
    asm volatile("cp.async.cg.shared.global [%0], [%1], 16;" :: "r"(dst), "l"(src))
#define CPCOMMIT() asm volatile("cp.async.commit_group;" ::: "memory")
#define CPWAIT(n)  asm volatile("cp.async.wait_group %0;" :: "n"(n) : "memory")

__device__ __forceinline__ void ldsm_x4(uint32_t* r, uint32_t addr) {
    asm volatile("ldmatrix.sync.aligned.m8n8.x4.shared.b16 {%0,%1,%2,%3}, [%4];"
                 : "=r"(r[0]), "=r"(r[1]), "=r"(r[2]), "=r"(r[3]) : "r"(addr));
}
__device__ __forceinline__ void ldsm_x4_t(uint32_t* r, uint32_t addr) {
    asm volatile("ldmatrix.sync.aligned.m8n8.x4.trans.shared.b16 {%0,%1,%2,%3}, [%4];"
                 : "=r"(r[0]), "=r"(r[1]), "=r"(r[2]), "=r"(r[3]) : "r"(addr));
}
__device__ __forceinline__ void mma_fp16(float* d, const uint32_t* a,
                                         uint32_t b0, uint32_t b1) {
    asm volatile(
        "mma.sync.aligned.m16n8k16.row.col.f32.f16.f16.f32 "
        "{%0,%1,%2,%3}, {%4,%5,%6,%7}, {%8,%9}, {%0,%1,%2,%3};"
        : "+f"(d[0]), "+f"(d[1]), "+f"(d[2]), "+f"(d[3])
        : "r"(a[0]), "r"(a[1]), "r"(a[2]), "r"(a[3]), "r"(b0), "r"(b1));
}
__device__ __forceinline__ uint32_t pack_h2(float a, float b) {
    __half2 h = __floats2half2_rn(a, b);
    return *(uint32_t*)&h;
}

// ---------------- fp16 split of X ----------------
__global__ __launch_bounds__(256) void convertX_kernel(const float* __restrict__ X) {
    size_t i = ((size_t)blockIdx.x * 256 + threadIdx.x) * 8;
    float4 a = *(const float4*)(X + i);
    float4 b = *(const float4*)(X + i + 4);
    float v[8] = {a.x, a.y, a.z, a.w, b.x, b.y, b.z, b.w};
    __half h[8], l[8];
#pragma unroll
    for (int j = 0; j < 8; j++) {
        h[j] = __float2half_rn(v[j]);
        l[j] = __float2half_rn(v[j] - __half2float(h[j]));
    }
    *(uint4*)&g_Xh[i] = *(const uint4*)h;
    *(uint4*)&g_Xl[i] = *(const uint4*)l;
}

// ---------------- convertA + fused denom (R13 version) ----------------
__global__ __launch_bounds__(256) void convertA_kernel(const float* __restrict__ Ag) {
    __shared__ float dsum[KK];
    int tid = threadIdx.x, lane = tid & 31;
    if (tid < KK) dsum[tid] = 0.0f;
    __syncthreads();
    size_t i = ((size_t)blockIdx.x * 256 + tid) * 8;
    float4 a = *(const float4*)(Ag + i);
    float4 b = *(const float4*)(Ag + i + 4);
    float v[8] = {a.x, a.y, a.z, a.w, b.x, b.y, b.z, b.w};
    __half h[8];
#pragma unroll
    for (int j = 0; j < 8; j++) h[j] = __float2half_rn(v[j]);
    *(uint4*)&g_Ah[i] = *(const uint4*)h;
#pragma unroll
    for (int j = 0; j < 8; j++) {
        v[j] += __shfl_down_sync(0xffffffffu, v[j], 16);
        v[j] += __shfl_down_sync(0xffffffffu, v[j], 8);
    }
    if (lane < 8) {
        int k0 = (tid & 7) * 8;
#pragma unroll
        for (int j = 0; j < 8; j++) atomicAdd(&dsum[k0 + j], v[j]);
    }
    __syncthreads();
    int b_ = blockIdx.x >> 9;
    if (tid < KK) atomicAdd(&g_denom[b_ * KK + tid], dsum[tid]);
}

// ---------------- bias = A @ cluster_bias -> fp16 (register-accumulating) --------
__global__ __launch_bounds__(256) void bias_kernel(const float* __restrict__ Ag,
                                                   const float* __restrict__ cb) {
    __shared__ float cb_s[KK*KK];
    int tid = threadIdx.x;
    {
        const float4* cb4 = (const float4*)cb;
        float4* cbs4 = (float4*)cb_s;
        for (int i = tid; i < KK*KK/4; i += 256) cbs4[i] = cb4[i];
    }
    __syncthreads();
    size_t n = (size_t)blockIdx.x * 256 + tid;
    float biasr[64];
#pragma unroll
    for (int l = 0; l < 64; l++) biasr[l] = 0.0f;
    const float4* arow = (const float4*)(Ag + n * KK);
#pragma unroll
    for (int k4 = 0; k4 < 16; k4++) {
        float4 a4 = arow[k4];
        float avv[4] = {a4.x, a4.y, a4.z, a4.w};
#pragma unroll
        for (int kk = 0; kk < 4; kk++) {
            const float4* cbr = (const float4*)(cb_s + (k4 * 4 + kk) * 64);
#pragma unroll
            for (int l4 = 0; l4 < 16; l4++) {
                float4 c4 = cbr[l4];
                biasr[l4*4+0] += avv[kk] * c4.x;
                biasr[l4*4+1] += avv[kk] * c4.y;
                biasr[l4*4+2] += avv[kk] * c4.z;
                biasr[l4*4+3] += avv[kk] * c4.w;
            }
        }
    }
    uint32_t* dst = (uint32_t*)(g_biash + n * KK);
#pragma unroll
    for (int l2 = 0; l2 < 32; l2++)
        dst[l2] = pack_h2(biasr[l2*2], biasr[l2*2+1]);
}

// ---------------- transposed fp16 hi/lo weights ----------------
__global__ __launch_bounds__(256) void prepW_kernel(const float* __restrict__ wqkv,
                                                    const float* __restrict__ wproj) {
    int n = blockIdx.x, k = threadIdx.x;
    float wq = wqkv[k * (3*CC) + n];
    float wp = wproj[k * CC + n];
    __half qh = __float2half_rn(wq);
    __half ph = __float2half_rn(wp);
    int o = n * CC + k;
    g_Wqt_hi[o] = qh;
    g_Wqt_lo[o] = __float2half_rn(wq - __half2float(qh));
    g_Wpt_hi[o] = ph;
    g_Wpt_lo[o] = __float2half_rn(wp - __half2float(ph));
}

// ---------------- tensor-core pooling (unchanged) ----------------
#define PX_ST 264
#define PA_ST 72
#define PX_SIZE (64*PX_ST)
#define PA_SIZE (64*PA_ST)
#define POOL_SMEM ((3*PX_SIZE + 3*PA_SIZE)*2)
__global__ __launch_bounds__(256, 1) void pool_tc_kernel() {
    extern __shared__ __half ps[];
    uint32_t sb = smem_u32(ps);
    int tid = threadIdx.x, lane = tid & 31, w = tid >> 5;
    int wm = w >> 2, wn = w & 3;
    int b = blockIdx.x >> 5;
    int nbase = (blockIdx.x & 31) * 512;
    const __half* Asrc[2] = {g_Ah, g_Ah};
    const __half* Xsrc[2] = {g_Xh, g_Xl};

    float acc[2][8][4];
#pragma unroll
    for (int i = 0; i < 2; i++)
#pragma unroll
        for (int j = 0; j < 8; j++)
#pragma unroll
            for (int r = 0; r < 4; r++) acc[i][j][r] = 0.0f;

    auto issue = [&](int c) {
        int s = c >> 3, kc_ = c & 7, buf = c % 3;
        size_t grow0 = (size_t)b * NN + nbase + kc_ * 64;
#pragma unroll
        for (int i = 0; i < 8; i++) {
            int idx = tid + i * 256;
            int row = idx >> 5, ch = idx & 31;
            CP16(sb + (uint32_t)(buf * PX_SIZE + row * PX_ST + ch * 8) * 2,
                 Xsrc[s] + (grow0 + row) * CC + ch * 8);
        }
#pragma unroll
        for (int i = 0; i < 2; i++) {
            int idx = tid + i * 256;
            int row = idx >> 3, ch = idx & 7;
            CP16(sb + (uint32_t)(3 * PX_SIZE + buf * PA_SIZE + row * PA_ST + ch * 8) * 2,
                 Asrc[s] + (grow0 + row) * KK + ch * 8);
        }
        CPCOMMIT();
    };

    issue(0); issue(1);
#pragma unroll 1
    for (int c = 0; c < 16; c++) {
        if (c < 14) { CPWAIT(1); } else { CPWAIT(0); }
        __syncthreads();
        if (c + 2 < 16) issue(c + 2);
        int buf = c % 3;
        uint32_t xb = sb + (uint32_t)(buf * PX_SIZE) * 2;
        uint32_t ab = sb + (uint32_t)(3 * PX_SIZE + buf * PA_SIZE) * 2;
#pragma unroll
        for (int kt = 0; kt < 4; kt++) {
            uint32_t af[2][4];
#pragma unroll
            for (int mt = 0; mt < 2; mt++) {
                uint32_t r[4];
                ldsm_x4_t(r, ab + (uint32_t)((kt * 16 + (lane & 15)) * PA_ST +
                                             wm * 32 + mt * 16 + (lane >> 4) * 8) * 2);
                af[mt][0] = r[0]; af[mt][1] = r[2]; af[mt][2] = r[1]; af[mt][3] = r[3];
            }
#pragma unroll
            for (int nb = 0; nb < 4; nb++) {
                uint32_t bfr[4];
                ldsm_x4_t(bfr, xb + (uint32_t)((kt * 16 + (lane & 15)) * PX_ST +
                                               wn * 64 + nb * 16 + (lane >> 4) * 8) * 2);
#pragma unroll
                for (int mt = 0; mt < 2; mt++) {
                    mma_fp16(acc[mt][nb*2],   af[mt], bfr[0], bfr[1]);
                    mma_fp16(acc[mt][nb*2+1], af[mt], bfr[2], bfr[3]);
                }
            }
        }
    }
#pragma unroll
    for (int mt = 0; mt < 2; mt++)
#pragma unroll
        for (int nt = 0; nt < 8; nt++) {
            int cl = wm * 32 + mt * 16 + (lane >> 2);
            int col = wn * 64 + nt * 8 + 2 * (lane & 3);
            float* d0 = &g_S[(b * KK + cl) * CC + col];
            atomicAdd(d0,     acc[mt][nt][0]);
            atomicAdd(d0 + 1, acc[mt][nt][1]);
            float* d1 = &g_S[(b * KK + cl + 8) * CC + col];
            atomicAdd(d1,     acc[mt][nt][2]);
            atomicAdd(d1 + 1, acc[mt][nt][3]);
        }
}

// ---------------- kc/vc from S -> scaled fp16 2-term splits ----------------
__global__ __launch_bounds__(256) void kcvc_kernel(const float* __restrict__ wqkv) {
    int bk = blockIdx.x;
    int b = bk >> 6;
    int k = bk & 63;
    int t = threadIdx.x;
    __shared__ float s_row[CC];
    s_row[t] = g_S[bk * CC + t];
    __syncthreads();
    float inv = 1.0f / (g_denom[bk] + 1e-8f);
    float ak = 0.0f, av = 0.0f;
#pragma unroll 8
    for (int c = 0; c < CC; c++) {
        float s = s_row[c];
        ak += s * wqkv[c * (3*CC) + CC  + t];
        av += s * wqkv[c * (3*CC) + 2*CC + t];
    }
    int h = t >> 5, dd = t & 31;
    const float SC = 0.17677669529663689f;
    float kcv = ak * inv * SC;
    float vcv = av * inv;
    size_t ok = ((size_t)(b * HH + h) * KK + k) * DD + dd;
    size_t ov = ((size_t)(b * HH + h) * DD + dd) * KK + k;
    __half kh = __float2half_rn(kcv);
    __half vh = __float2half_rn(vcv);
    g_kchi[ok] = kh;  g_kclo[ok] = __float2half_rn(kcv - __half2float(kh));
    g_vcThi[ov] = vh; g_vcTlo[ov] = __float2half_rn(vcv - __half2float(vh));
}

// ---------------- HMMA fp16 2-term GEMM (unchanged) ----------------
#define AST 40
#define TILE_ELE (128 * AST)
#define STAGE_ELE (3 * TILE_ELE)
#define GEMM_SMEM_BYTES (3 * STAGE_ELE * 2)
__global__ __launch_bounds__(256, 2) void gemm_fp16x2_mma(
    const __half* __restrict__ Am, int a_planar,
    const __half* __restrict__ Whi, const __half* __restrict__ Wlo,
    const float* __restrict__ bias, float* __restrict__ Cout,
    __half* __restrict__ Oh) {
    extern __shared__ __half smemh[];
    uint32_t s_base = smem_u32(smemh);

    int tid = threadIdx.x;
    int lane = tid & 31, w = tid >> 5;
    int wr = w >> 2, wc = w & 3;
    size_t mbase = (size_t)blockIdx.x * 128;
    int nbase = blockIdx.y * 128;

    int ldrow = tid >> 1;
    int ldw0  = (tid & 1) * 2;

    float acc[4][4][4];
#pragma unroll
    for (int i = 0; i < 4; i++)
#pragma unroll
        for (int j = 0; j < 4; j++)
#pragma unroll
            for (int r = 0; r < 4; r++) acc[i][j][r] = 0.0f;

    auto issue = [&](int c) {
        int ko = c * 32;
        uint32_t sa = s_base + (uint32_t)((c % 3) * STAGE_ELE) * 2;
        const __half* Abase = a_planar
            ? Am + ((size_t)c * BNTOT + mbase + ldrow) * 32
            : Am + (mbase + ldrow) * CC + ko;
#pragma unroll
        for (int j = 0; j < 2; j++) {
            int cw = ldw0 + j;
            uint32_t d = (uint32_t)(ldrow * AST + cw * 8) * 2;
            CP16(sa + d,                    Abase + cw * 8);
            CP16(sa + d + TILE_ELE * 2,     Whi + (size_t)(nbase + ldrow) * CC + ko + cw * 8);
            CP16(sa + d + 2 * TILE_ELE * 2, Wlo + (size_t)(nbase + ldrow) * CC + ko + cw * 8);
        }
        CPCOMMIT();
    };

    int arow = (lane & 7) + 8 * ((lane >> 3) & 1);
    int akw  = (lane >> 4) * 8;
    int brow = (lane & 7) + 8 * ((lane >> 4) & 1);
    int bkw  = ((lane >> 3) & 1) * 8;

    auto compute = [&](int stage) {
        uint32_t sa  = s_base + (uint32_t)(stage * STAGE_ELE) * 2;
        uint32_t sbh = sa + (uint32_t)TILE_ELE * 2;
        uint32_t sbl = sa + (uint32_t)(2 * TILE_ELE) * 2;
#pragma unroll
        for (int ks = 0; ks < 32; ks += 16) {
            uint32_t afr[4][4];
#pragma unroll
            for (int mt = 0; mt < 4; mt++)
                ldsm_x4(afr[mt], sa + (uint32_t)(((wr * 64 + mt * 16 + arow) * AST) + ks + akw) * 2);
            uint32_t bh[2][4], bl[2][4];
#pragma unroll
            for (int nt2 = 0; nt2 < 2; nt2++) {
                uint32_t off = (uint32_t)(((wc * 32 + nt2 * 16 + brow) * AST) + ks + bkw) * 2;
                ldsm_x4(bh[nt2], sbh + off);
                ldsm_x4(bl[nt2], sbl + off);
            }
#pragma unroll
            for (int mt = 0; mt < 4; mt++)
#pragma unroll
                for (int nt = 0; nt < 4; nt++) {
                    mma_fp16(acc[mt][nt], afr[mt],
                             bh[nt >> 1][(nt & 1) * 2], bh[nt >> 1][(nt & 1) * 2 + 1]);
                    mma_fp16(acc[mt][nt], afr[mt],
                             bl[nt >> 1][(nt & 1) * 2], bl[nt >> 1][(nt & 1) * 2 + 1]);
                }
        }
    };

    issue(0);
    issue(1);
#pragma unroll 1
    for (int c = 0; c < 8; c++) {
        if (c < 6) { CPWAIT(1); } else { CPWAIT(0); }
        __syncthreads();
        if (c + 2 < 8) issue(c + 2);
        compute(c % 3);
    }

    int g = lane >> 2, ti = lane & 3;
#pragma unroll
    for (int mt = 0; mt < 4; mt++) {
#pragma unroll
        for (int nt = 0; nt < 4; nt++) {
            size_t row = mbase + wr * 64 + mt * 16 + g;
            int col = nbase + wc * 32 + nt * 8 + ti * 2;
            if (Cout) {
                float bx = 0.0f, by = 0.0f;
                if (bias) { bx = bias[col]; by = bias[col + 1]; }
                float2 v0, v1;
                v0.x = acc[mt][nt][0] + bx; v0.y = acc[mt][nt][1] + by;
                v1.x = acc[mt][nt][2] + bx; v1.y = acc[mt][nt][3] + by;
                *(float2*)&Cout[row * CC + col] = v0;
                *(float2*)&Cout[(row + 8) * CC + col] = v1;
            } else {
                int hh = col >> 5, dd0 = col & 31;
                size_t o0 = ((size_t)hh * BNTOT + row) * 32 + dd0;
                size_t o1 = ((size_t)hh * BNTOT + row + 8) * 32 + dd0;
                *(uint32_t*)&Oh[o0] = pack_h2(acc[mt][nt][0], acc[mt][nt][1]);
                *(uint32_t*)&Oh[o1] = pack_h2(acc[mt][nt][2], acc[mt][nt][3]);
            }
        }
    }
}

// ---------------- tensor-core attention (R13 config; fp16 bias from global) ----------
#define ATT_BUF_BYTES 19456
#define ATT_SMEM_BYTES (2 * ATT_BUF_BYTES)
__global__ __launch_bounds__(256, 2) void attn_tc_kernel() {
    extern __shared__ __half smn[];
    uint32_t sb = smem_u32(smn);
    int tid = threadIdx.x, lane = tid & 31, w = tid >> 5;
    size_t tok0 = (size_t)blockIdx.x * 128;
    int b = blockIdx.x >> 7;
    int r = lane >> 2, c = lane & 3;
    size_t trow0 = tok0 + (size_t)w * 16 + r;
    size_t trow1 = trow0 + 8;

    const uint32_t KHI = 0, KLO = 5120, VHI = 10240, VLO = 14848;

    auto issue_head = [&](int h) {
        uint32_t bo = (uint32_t)(h & 1) * ATT_BUF_BYTES;
        {
            int rr = tid >> 2, cc = tid & 3;
            size_t src = ((size_t)(b * HH + h) * KK + rr) * DD + cc * 8;
            uint32_t d = (uint32_t)(rr * 40 + cc * 8) * 2;
            CP16(sb + bo + KHI + d, g_kchi + src);
            CP16(sb + bo + KLO + d, g_kclo + src);
        }
        {
            int rr = tid >> 3, cc = tid & 7;
            size_t src = ((size_t)(b * HH + h) * DD + rr) * KK + cc * 8;
            uint32_t d = (uint32_t)(rr * 72 + cc * 8) * 2;
            CP16(sb + bo + VHI + d, g_vcThi + src);
            CP16(sb + bo + VLO + d, g_vcTlo + src);
        }
        CPCOMMIT();
    };
    issue_head(0);

    int brow = (lane & 7) + 8 * ((lane >> 4) & 1);
    int bkw  = ((lane >> 3) & 1) * 8;

#pragma unroll 1
    for (int h = 0; h < HH; h++) {
        CPWAIT(0);
        __syncthreads();
        if (h + 1 < HH) issue_head(h + 1);
        uint32_t bo = (uint32_t)(h & 1) * ATT_BUF_BYTES;

        const __half* q_base = g_qh + (size_t)h * BNTOT * 32;
        uint32_t q[2][4];
#pragma unroll
        for (int ks = 0; ks < 2; ks++) {
            int col = ks * 16 + c * 2;
            q[ks][0] = *(const uint32_t*)(q_base + trow0 * 32 + col);
            q[ks][1] = *(const uint32_t*)(q_base + trow1 * 32 + col);
            q[ks][2] = *(const uint32_t*)(q_base + trow0 * 32 + col + 8);
            q[ks][3] = *(const uint32_t*)(q_base + trow1 * 32 + col + 8);
        }

        // logits init with fp16 bias rows (L2-resident after head 0)
        float L[8][4];
#pragma unroll
        for (int t = 0; t < 8; t++) {
            __half2 b0 = *(const __half2*)(g_biash + trow0 * KK + t * 8 + c * 2);
            __half2 b1 = *(const __half2*)(g_biash + trow1 * KK + t * 8 + c * 2);
            float2 f0 = __half22float2(b0);
            float2 f1 = __half22float2(b1);
            L[t][0] = f0.x; L[t][1] = f0.y;
            L[t][2] = f1.x; L[t][3] = f1.y;
        }
#pragma unroll
        for (int g2 = 0; g2 < 4; g2++) {
#pragma unroll
            for (int ks = 0; ks < 2; ks++) {
                uint32_t bh[4], bl[4];
                uint32_t ad = (uint32_t)((g2 * 16 + brow) * 40 + ks * 16 + bkw) * 2;
                ldsm_x4(bh, sb + bo + KHI + ad);
                ldsm_x4(bl, sb + bo + KLO + ad);
                mma_fp16(L[2*g2],   q[ks], bh[0], bh[1]);
                mma_fp16(L[2*g2],   q[ks], bl[0], bl[1]);
                mma_fp16(L[2*g2+1], q[ks], bh[2], bh[3]);
                mma_fp16(L[2*g2+1], q[ks], bl[2], bl[3]);
            }
        }

        float m0 = -1e30f, m1 = -1e30f;
#pragma unroll
        for (int t = 0; t < 8; t++) {
            m0 = fmaxf(m0, fmaxf(L[t][0], L[t][1]));
            m1 = fmaxf(m1, fmaxf(L[t][2], L[t][3]));
        }
        m0 = fmaxf(m0, __shfl_xor_sync(0xffffffffu, m0, 1));
        m0 = fmaxf(m0, __shfl_xor_sync(0xffffffffu, m0, 2));
        m1 = fmaxf(m1, __shfl_xor_sync(0xffffffffu, m1, 1));
        m1 = fmaxf(m1, __shfl_xor_sync(0xffffffffu, m1, 2));
        float s0 = 0.0f, s1 = 0.0f;
#pragma unroll
        for (int t = 0; t < 8; t++) {
            L[t][0] = __expf(L[t][0] - m0); s0 += L[t][0];
            L[t][1] = __expf(L[t][1] - m0); s0 += L[t][1];
            L[t][2] = __expf(L[t][2] - m1); s1 += L[t][2];
            L[t][3] = __expf(L[t][3] - m1); s1 += L[t][3];
        }
        s0 += __shfl_xor_sync(0xffffffffu, s0, 1);
        s0 += __shfl_xor_sync(0xffffffffu, s0, 2);
        s1 += __shfl_xor_sync(0xffffffffu, s1, 1);
        s1 += __shfl_xor_sync(0xffffffffu, s1, 2);
        float inv0 = 1.0f / s0, inv1 = 1.0f / s1;

        float O[4][4];
#pragma unroll
        for (int t = 0; t < 4; t++)
#pragma unroll
            for (int v = 0; v < 4; v++) O[t][v] = 0.0f;
#pragma unroll
        for (int kc_ = 0; kc_ < 4; kc_++) {
            uint32_t p[4];
            p[0] = pack_h2(L[2*kc_][0] * inv0,   L[2*kc_][1] * inv0);
            p[1] = pack_h2(L[2*kc_][2] * inv1,   L[2*kc_][3] * inv1);
            p[2] = pack_h2(L[2*kc_+1][0] * inv0, L[2*kc_+1][1] * inv0);
            p[3] = pack_h2(L[2*kc_+1][2] * inv1, L[2*kc_+1][3] * inv1);
#pragma unroll
            for (int g2 = 0; g2 < 2; g2++) {
                uint32_t bh[4], bl[4];
                uint32_t ad = (uint32_t)((g2 * 16 + brow) * 72 + kc_ * 16 + bkw) * 2;
                ldsm_x4(bh, sb + bo + VHI + ad);
                ldsm_x4(bl, sb + bo + VLO + ad);
                mma_fp16(O[2*g2],   p, bh[0], bh[1]);
                mma_fp16(O[2*g2],   p, bl[0], bl[1]);
                mma_fp16(O[2*g2+1], p, bh[2], bh[3]);
                mma_fp16(O[2*g2+1], p, bl[2], bl[3]);
            }
        }

        __half* xh_base = g_xh + (size_t)h * BNTOT * 32;
#pragma unroll
        for (int nt = 0; nt < 4; nt++) {
            int col = nt * 8 + c * 2;
            *(uint32_t*)&xh_base[trow0 * 32 + col] = pack_h2(O[nt][0], O[nt][1]);
            *(uint32_t*)&xh_base[trow1 * 32 + col] = pack_h2(O[nt][2], O[nt][3]);
        }
    }
}

// ---------------- launcher ----------------
extern "C" void kernel_launch(void* const* d_in, const int* in_sizes, int n_in,
                              void* d_out, int out_size) {
    const float* X     = (const float*)d_in[0];
    const float* Ag    = (const float*)d_in[1];
    const float* wqkv  = (const float*)d_in[2];
    const float* wproj = (const float*)d_in[3];
    const float* bproj = (const float*)d_in[4];
    const float* cb    = (const float*)d_in[5];
    float* out = (float*)d_out;

    __half *pXh, *pxh, *pqh, *pWqh, *pWql, *pWph, *pWpl;
    float *pS, *pden;
    cudaGetSymbolAddress((void**)&pXh, g_Xh);
    cudaGetSymbolAddress((void**)&pxh, g_xh);
    cudaGetSymbolAddress((void**)&pqh, g_qh);
    cudaGetSymbolAddress((void**)&pWqh, g_Wqt_hi);
    cudaGetSymbolAddress((void**)&pWql, g_Wqt_lo);
    cudaGetSymbolAddress((void**)&pWph, g_Wpt_hi);
    cudaGetSymbolAddress((void**)&pWpl, g_Wpt_lo);
    cudaGetSymbolAddress((void**)&pS, g_S);
    cudaGetSymbolAddress((void**)&pden, g_denom);

    cudaFuncSetAttribute(gemm_fp16x2_mma,
                         cudaFuncAttributeMaxDynamicSharedMemorySize, GEMM_SMEM_BYTES);
    cudaFuncSetAttribute(pool_tc_kernel,
                         cudaFuncAttributeMaxDynamicSharedMemorySize, POOL_SMEM);
    cudaFuncSetAttribute(attn_tc_kernel,
                         cudaFuncAttributeMaxDynamicSharedMemorySize, ATT_SMEM_BYTES);

    cudaMemsetAsync(pS, 0, sizeof(float) * BB * KK * CC);
    cudaMemsetAsync(pden, 0, sizeof(float) * BB * KK);
    convertX_kernel<<<(BNTOT*CC) / (256*8), 256>>>(X);
    prepW_kernel<<<CC, 256>>>(wqkv, wproj);
    {   // Q = X @ Wq, single fp16 planar output
        dim3 grid(BNTOT / 128, CC / 128);
        gemm_fp16x2_mma<<<grid, 256, GEMM_SMEM_BYTES>>>(pXh, 0, pWqh, pWql,
                                                        nullptr, nullptr, pqh);
    }
    convertA_kernel<<<(BNTOT*KK) / (256*8), 256>>>(Ag);
    bias_kernel<<<BNTOT / 256, 256>>>(Ag, cb);
    pool_tc_kernel<<<BB * 32, 256, POOL_SMEM>>>();
    kcvc_kernel<<<BB * KK, 256>>>(wqkv);
    attn_tc_kernel<<<BNTOT / 128, 256, ATT_SMEM_BYTES>>>();
    {   // out = x @ Wproj + b
        dim3 grid(BNTOT / 128, CC / 128);
        gemm_fp16x2_mma<<<grid, 256, GEMM_SMEM_BYTES>>>(pxh, 1, pWph, pWpl,
                                                        bproj, out, nullptr);
    }
}